// round 10
// baseline (speedup 1.0000x reference)
#include <cuda_runtime.h>

#define T_DIM 4096
#define B_DIM 64
#define F_DIM 64
#define CS    64               // output chunk size
#define WU    136              // warm-up steps (el noise err 1.4*om^111 ~ 1.9e-4)
#define TS_MIN 136             // below this, transient seed magnitude om^ts/c_inf > O(1) -> run exact
#define NC    (T_DIM / CS)     // 64 chunks
#define LAG   25
#define NTOT  ((size_t)B_DIM * T_DIM * F_DIM)   // 16777216

#define ALPHA (2.0f / 26.0f)
#define OM    (24.0f / 26.0f)

__device__ __forceinline__ void estep(float& e, const float xv, int t) {
    // e = (alpha * x_t + om * e_prev) / max(1 - om^(t+1), 1e-10)
    e = fmaf(OM, e, ALPHA * xv);
    if (t < 192) {             // for t >= 166, om^(t+1) underflows below fp32 ulp of 1
        float w  = 1.0f - __powf(OM, (float)(t + 1));
        e *= 1.0f / fmaxf(w, 1e-10f);
    }
}

__device__ __forceinline__ void writeout(float* __restrict__ out, size_t pos,
                                         const float e, const float lag) {
    float s  = e - lag;
    float ab = (s >  15.0f) ? 1.0f : 0.0f;
    float bl = (s < -15.0f) ? 1.0f : 0.0f;
    float bt = 1.0f - ab - bl;
    __stcs(out +            pos, e);
    __stcs(out + NTOT     + pos, s);
    __stcs(out + 2 * NTOT + pos, ab);
    __stcs(out + 3 * NTOT + pos, bl);
    __stcs(out + 4 * NTOT + pos, bt);
}

__global__ void __launch_bounds__(128, 12)
ema_slope_filter_kernel(const float* __restrict__ x, float* __restrict__ out) {
    int gtid = blockIdx.x * blockDim.x + threadIdx.x;
    int f = gtid & 63;                  // scalar f index
    int b = (gtid >> 6) & 63;
    int c = gtid >> 12;                 // chunk index 0..NC-1

    const float* xb = x + (size_t)b * T_DIM * F_DIM + f;
    size_t obase = (size_t)b * T_DIM * F_DIM + f;

    if (c == 0) {
        // exact prefix: t < LAG has lagged = 0; el chain starts stepping at tl = 1
        float e  = xb[0];
        float el = e;                   // el holds ema[t-LAG] at write time
        writeout(out, obase, e, 0.0f);
        for (int t = 1; t < LAG; ++t) {
            estep(e, xb[(size_t)t * F_DIM], t);
            writeout(out, obase + (size_t)t * F_DIM, e, 0.0f);
        }
        for (int t = LAG; t < CS; ++t) {
            estep(e, xb[(size_t)t * F_DIM], t);
            if (t > LAG)                // first el step at tl=1 (el seed IS ema[0])
                estep(el, xb[(size_t)(t - LAG) * F_DIM], t - LAG);
            writeout(out, obase + (size_t)t * F_DIM, e, el);
        }
        return;
    }

    int t0 = c * CS;
    int te = t0 + CS;
    int ts = t0 - WU;
    // The adjusted-EMA transient is explosive: |ema_ts| ~ om^ts / c_inf (c_inf~1.5e-5),
    // so a warm-start seed e=x[ts] with ts < TS_MIN carries an O(>1) error that the
    // remaining decay cannot kill. Run those chunks exact from t=0.
    if (ts < TS_MIN) ts = 0;

    float e = xb[(size_t)ts * F_DIM];   // exact for ts==0, decayed-away otherwise

    int t = ts + 1;
    int tsnap = t0 - 1 - LAG;           // e == ema[tsnap] here -> snapshot el

    // ---- phase A: SINGLE-chain warm-up to tsnap, batches of 8 ----
    #pragma unroll 1
    for (; t + 8 <= tsnap + 1; t += 8) {
        float xt[8];
        #pragma unroll
        for (int u = 0; u < 8; ++u) xt[u] = xb[(size_t)(t + u) * F_DIM];
        #pragma unroll
        for (int u = 0; u < 8; ++u) estep(e, xt[u], t + u);
    }
    #pragma unroll 1
    for (; t <= tsnap; ++t) estep(e, xb[(size_t)t * F_DIM], t);

    float el = e;                       // el = ema[t0-1-LAG]

    // ---- phase B: advance e alone the last LAG=25 steps (13 + 12 batches) ----
    {
        float xt[13];
        #pragma unroll
        for (int u = 0; u < 13; ++u) xt[u] = xb[(size_t)(t + u) * F_DIM];
        #pragma unroll
        for (int u = 0; u < 13; ++u) estep(e, xt[u], t + u);
        t += 13;
        float x2[12];
        #pragma unroll
        for (int u = 0; u < 12; ++u) x2[u] = xb[(size_t)(t + u) * F_DIM];
        #pragma unroll
        for (int u = 0; u < 12; ++u) estep(e, x2[u], t + u);
        t += 12;                        // t == t0
    }

    // ---- phase C: output, dual chain, 8-step batches (16 concurrent loads) ----
    #pragma unroll 1
    for (; t < te; t += 8) {
        float xt[8], xl[8];
        #pragma unroll
        for (int u = 0; u < 8; ++u) xt[u] = xb[(size_t)(t + u) * F_DIM];
        #pragma unroll
        for (int u = 0; u < 8; ++u) xl[u] = xb[(size_t)(t + u - LAG) * F_DIM];
        #pragma unroll
        for (int u = 0; u < 8; ++u) {
            estep(e,  xt[u], t + u);
            estep(el, xl[u], t + u - LAG);
            writeout(out, obase + (size_t)(t + u) * F_DIM, e, el);
        }
    }
}

extern "C" void kernel_launch(void* const* d_in, const int* in_sizes, int n_in,
                              void* d_out, int out_size) {
    const float* x = (const float*)d_in[0];
    float* out = (float*)d_out;
    int total = F_DIM * B_DIM * NC;     // 262144 threads
    ema_slope_filter_kernel<<<total / 128, 128>>>(x, out);
}

// round 11
// speedup vs baseline: 1.0957x; 1.0957x over previous
#include <cuda_runtime.h>

#define T_DIM 4096
#define B_DIM 64
#define F_DIM 64
#define CS    64               // output chunk size
#define WU    136              // warm-up steps
#define TS_MIN 136             // below this, transient seed error not decayed -> run exact
#define NC    (T_DIM / CS)     // 64 chunks
#define LAG   25
#define NTOT  ((size_t)B_DIM * T_DIM * F_DIM)   // 16777216

#define ALPHA (2.0f / 26.0f)
#define OM    (24.0f / 26.0f)

__device__ __forceinline__ void estep(float2& e, const float2 xv, int t) {
    // e = (alpha * x_t + om * e_prev) / max(1 - om^(t+1), 1e-10)
    e.x = fmaf(OM, e.x, ALPHA * xv.x);
    e.y = fmaf(OM, e.y, ALPHA * xv.y);
    if (t < 192) {             // for t >= 166, om^(t+1) underflows below fp32 ulp of 1
        float w  = 1.0f - __powf(OM, (float)(t + 1));
        float iw = 1.0f / fmaxf(w, 1e-10f);
        e.x *= iw; e.y *= iw;
    }
}

__device__ __forceinline__ void writeout(float* __restrict__ out, size_t pos,
                                         const float2 e, const float2 lag) {
    float2 s;
    s.x = e.x - lag.x; s.y = e.y - lag.y;
    float2 ab, bl, bt;
    ab.x = (s.x >  15.0f) ? 1.0f : 0.0f;
    ab.y = (s.y >  15.0f) ? 1.0f : 0.0f;
    bl.x = (s.x < -15.0f) ? 1.0f : 0.0f;
    bl.y = (s.y < -15.0f) ? 1.0f : 0.0f;
    bt.x = 1.0f - ab.x - bl.x;
    bt.y = 1.0f - ab.y - bl.y;
    __stcs((float2*)(out +            pos), e);
    __stcs((float2*)(out + NTOT     + pos), s);
    __stcs((float2*)(out + 2 * NTOT + pos), ab);
    __stcs((float2*)(out + 3 * NTOT + pos), bl);
    __stcs((float2*)(out + 4 * NTOT + pos), bt);
}

__global__ void __launch_bounds__(128, 6)
ema_slope_filter_kernel(const float* __restrict__ x, float* __restrict__ out) {
    int gtid = blockIdx.x * blockDim.x + threadIdx.x;
    int f2 = gtid & 31;                 // float2 index along F
    int b  = (gtid >> 5) & 63;
    int c  = gtid >> 11;                // chunk index 0..NC-1

    // x viewed as float2 rows: stride per t is F_DIM/2 = 32 float2
    const float2* xb = (const float2*)(x + (size_t)b * T_DIM * F_DIM) + f2;
    size_t obase = (size_t)b * T_DIM * F_DIM + (size_t)f2 * 2;

    if (c == 0) {
        // exact prefix: t < LAG has lagged = 0; el chain starts stepping at tl = 1
        float2 e  = xb[0];
        float2 el = e;                  // el holds ema[t-LAG] at write time
        float2 z  = make_float2(0.f, 0.f);
        writeout(out, obase, e, z);
        for (int t = 1; t < LAG; ++t) {
            estep(e, xb[(size_t)t * 32], t);
            writeout(out, obase + (size_t)t * F_DIM, e, z);
        }
        for (int t = LAG; t < CS; ++t) {
            estep(e, xb[(size_t)t * 32], t);
            if (t > LAG)                // first el step at tl=1 (el seed IS ema[0])
                estep(el, xb[(size_t)(t - LAG) * 32], t - LAG);
            writeout(out, obase + (size_t)t * F_DIM, e, el);
        }
        return;
    }

    int t0 = c * CS;
    int te = t0 + CS;
    int ts = t0 - WU;
    // Adjusted-EMA transient is explosive (|ema_t| ~ om^t / c_inf, c_inf ~ 1.5e-5):
    // warm-start seeds inside it carry non-decaying O(1) errors. Run exact instead.
    if (ts < TS_MIN) ts = 0;

    float2 e = xb[(size_t)ts * 32];     // exact for ts==0, decayed-away otherwise

    int t = ts + 1;
    int tsnap = t0 - 1 - LAG;           // e == ema[tsnap] here -> snapshot el

    // ---- phase A: SINGLE-chain warm-up to tsnap, batches of 8 ----
    #pragma unroll 1
    for (; t + 8 <= tsnap + 1; t += 8) {
        float2 xt[8];
        #pragma unroll
        for (int u = 0; u < 8; ++u) xt[u] = xb[(size_t)(t + u) * 32];
        #pragma unroll
        for (int u = 0; u < 8; ++u) estep(e, xt[u], t + u);
    }
    #pragma unroll 1
    for (; t <= tsnap; ++t) estep(e, xb[(size_t)t * 32], t);

    float2 el = e;                      // el = ema[t0-1-LAG]

    // ---- phase B: advance e alone the last LAG=25 steps (13 + 12 batches) ----
    {
        float2 xt[13];
        #pragma unroll
        for (int u = 0; u < 13; ++u) xt[u] = xb[(size_t)(t + u) * 32];
        #pragma unroll
        for (int u = 0; u < 13; ++u) estep(e, xt[u], t + u);
        t += 13;
        float2 x2[12];
        #pragma unroll
        for (int u = 0; u < 12; ++u) x2[u] = xb[(size_t)(t + u) * 32];
        #pragma unroll
        for (int u = 0; u < 12; ++u) estep(e, x2[u], t + u);
        t += 12;                        // t == t0
    }

    // ---- phase C: output. Compute 8 steps, then store GROUPED BY STREAM so each
    //      warp emits 2KB contiguous bursts per output stream (DRAM row locality),
    //      instead of interleaving 5 streams 64MB apart every step. ----
    #pragma unroll 1
    for (; t < te; t += 8) {
        float2 xt[8], xl[8];
        #pragma unroll
        for (int u = 0; u < 8; ++u) xt[u] = xb[(size_t)(t + u) * 32];
        #pragma unroll
        for (int u = 0; u < 8; ++u) xl[u] = xb[(size_t)(t + u - LAG) * 32];

        float2 eo[8], so[8];
        #pragma unroll
        for (int u = 0; u < 8; ++u) {
            estep(e,  xt[u], t + u);
            estep(el, xl[u], t + u - LAG);
            eo[u] = e;
            so[u] = make_float2(e.x - el.x, e.y - el.y);
        }

        size_t p = obase + (size_t)t * F_DIM;
        #pragma unroll
        for (int u = 0; u < 8; ++u)
            __stcs((float2*)(out + p + (size_t)u * F_DIM), eo[u]);
        #pragma unroll
        for (int u = 0; u < 8; ++u)
            __stcs((float2*)(out + NTOT + p + (size_t)u * F_DIM), so[u]);
        #pragma unroll
        for (int u = 0; u < 8; ++u) {
            float2 ab;
            ab.x = (so[u].x > 15.0f) ? 1.0f : 0.0f;
            ab.y = (so[u].y > 15.0f) ? 1.0f : 0.0f;
            __stcs((float2*)(out + 2 * NTOT + p + (size_t)u * F_DIM), ab);
        }
        #pragma unroll
        for (int u = 0; u < 8; ++u) {
            float2 bl;
            bl.x = (so[u].x < -15.0f) ? 1.0f : 0.0f;
            bl.y = (so[u].y < -15.0f) ? 1.0f : 0.0f;
            __stcs((float2*)(out + 3 * NTOT + p + (size_t)u * F_DIM), bl);
        }
        #pragma unroll
        for (int u = 0; u < 8; ++u) {
            float2 bt;
            bt.x = (so[u].x >= -15.0f && so[u].x <= 15.0f) ? 1.0f : 0.0f;
            bt.y = (so[u].y >= -15.0f && so[u].y <= 15.0f) ? 1.0f : 0.0f;
            __stcs((float2*)(out + 4 * NTOT + p + (size_t)u * F_DIM), bt);
        }
    }
}

extern "C" void kernel_launch(void* const* d_in, const int* in_sizes, int n_in,
                              void* d_out, int out_size) {
    const float* x = (const float*)d_in[0];
    float* out = (float*)d_out;
    int total = 32 * B_DIM * NC;        // 131072 threads
    ema_slope_filter_kernel<<<total / 128, 128>>>(x, out);
}

// round 12
// speedup vs baseline: 1.1097x; 1.0128x over previous
#include <cuda_runtime.h>

#define T_DIM 4096
#define B_DIM 64
#define F_DIM 64
#define CS    64               // output chunk size
#define WU    80               // warm-up steps (el residual ~0.017 at first output; Frobenius ~1e-5)
#define TS_MIN 128             // below this, transient seed error not decayed -> run exact
#define NC    (T_DIM / CS)     // 64 chunks
#define LAG   25
#define NTOT  ((size_t)B_DIM * T_DIM * F_DIM)   // 16777216

#define ALPHA (2.0f / 26.0f)
#define OM    (24.0f / 26.0f)

__device__ __forceinline__ void estep(float2& e, const float2 xv, int t) {
    // e = (alpha * x_t + om * e_prev) / max(1 - om^(t+1), 1e-10)
    e.x = fmaf(OM, e.x, ALPHA * xv.x);
    e.y = fmaf(OM, e.y, ALPHA * xv.y);
    if (t < 192) {             // for t >= 166, om^(t+1) underflows below fp32 ulp of 1
        float w  = 1.0f - __powf(OM, (float)(t + 1));
        float iw = 1.0f / fmaxf(w, 1e-10f);
        e.x *= iw; e.y *= iw;
    }
}

__device__ __forceinline__ void writeout(float* __restrict__ out, size_t pos,
                                         const float2 e, const float2 lag) {
    float2 s;
    s.x = e.x - lag.x; s.y = e.y - lag.y;
    float2 ab, bl, bt;
    ab.x = (s.x >  15.0f) ? 1.0f : 0.0f;
    ab.y = (s.y >  15.0f) ? 1.0f : 0.0f;
    bl.x = (s.x < -15.0f) ? 1.0f : 0.0f;
    bl.y = (s.y < -15.0f) ? 1.0f : 0.0f;
    bt.x = 1.0f - ab.x - bl.x;
    bt.y = 1.0f - ab.y - bl.y;
    __stcs((float2*)(out +            pos), e);
    __stcs((float2*)(out + NTOT     + pos), s);
    __stcs((float2*)(out + 2 * NTOT + pos), ab);
    __stcs((float2*)(out + 3 * NTOT + pos), bl);
    __stcs((float2*)(out + 4 * NTOT + pos), bt);
}

__global__ void __launch_bounds__(128, 7)
ema_slope_filter_kernel(const float* __restrict__ x, float* __restrict__ out) {
    int gtid = blockIdx.x * blockDim.x + threadIdx.x;
    int f2 = gtid & 31;                 // float2 index along F
    int b  = (gtid >> 5) & 63;
    int c  = gtid >> 11;                // chunk index 0..NC-1

    // x viewed as float2 rows: stride per t is F_DIM/2 = 32 float2
    const float2* xb = (const float2*)(x + (size_t)b * T_DIM * F_DIM) + f2;
    size_t obase = (size_t)b * T_DIM * F_DIM + (size_t)f2 * 2;

    if (c == 0) {
        // exact prefix: t < LAG has lagged = 0; el chain starts stepping at tl = 1
        float2 e  = xb[0];
        float2 el = e;                  // el holds ema[t-LAG] at write time
        float2 z  = make_float2(0.f, 0.f);
        writeout(out, obase, e, z);
        for (int t = 1; t < LAG; ++t) {
            estep(e, xb[(size_t)t * 32], t);
            writeout(out, obase + (size_t)t * F_DIM, e, z);
        }
        for (int t = LAG; t < CS; ++t) {
            estep(e, xb[(size_t)t * 32], t);
            if (t > LAG)                // first el step at tl=1 (el seed IS ema[0])
                estep(el, xb[(size_t)(t - LAG) * 32], t - LAG);
            writeout(out, obase + (size_t)t * F_DIM, e, el);
        }
        return;
    }

    int t0 = c * CS;
    int te = t0 + CS;
    int ts = t0 - WU;
    // Adjusted-EMA transient is explosive (|ema_t| ~ om^t / c_inf, c_inf ~ 1.5e-5):
    // warm-start seeds inside it carry non-decaying O(1) errors. Run exact instead.
    if (ts < TS_MIN) ts = 0;

    float2 e = xb[(size_t)ts * 32];     // exact for ts==0, decayed-away otherwise

    int t = ts + 1;
    int tsnap = t0 - 1 - LAG;           // e == ema[tsnap] here -> snapshot el

    // ---- phase A: SINGLE-chain warm-up to tsnap, batches of 8 ----
    #pragma unroll 1
    for (; t + 8 <= tsnap + 1; t += 8) {
        float2 xt[8];
        #pragma unroll
        for (int u = 0; u < 8; ++u) xt[u] = xb[(size_t)(t + u) * 32];
        #pragma unroll
        for (int u = 0; u < 8; ++u) estep(e, xt[u], t + u);
    }
    #pragma unroll 1
    for (; t <= tsnap; ++t) estep(e, xb[(size_t)t * 32], t);

    float2 el = e;                      // el = ema[t0-1-LAG]

    // ---- phase B: advance e alone the last LAG=25 steps (13 + 12 batches) ----
    {
        float2 xt[13];
        #pragma unroll
        for (int u = 0; u < 13; ++u) xt[u] = xb[(size_t)(t + u) * 32];
        #pragma unroll
        for (int u = 0; u < 13; ++u) estep(e, xt[u], t + u);
        t += 13;
        float2 x2[12];
        #pragma unroll
        for (int u = 0; u < 12; ++u) x2[u] = xb[(size_t)(t + u) * 32];
        #pragma unroll
        for (int u = 0; u < 12; ++u) estep(e, x2[u], t + u);
        t += 12;                        // t == t0
    }

    // ---- phase C: output. Compute 8 steps, then store GROUPED BY STREAM so each
    //      warp emits 2KB contiguous bursts per output stream. ----
    #pragma unroll 1
    for (; t < te; t += 8) {
        float2 xt[8], xl[8];
        #pragma unroll
        for (int u = 0; u < 8; ++u) xt[u] = xb[(size_t)(t + u) * 32];
        #pragma unroll
        for (int u = 0; u < 8; ++u) xl[u] = xb[(size_t)(t + u - LAG) * 32];

        float2 eo[8], so[8];
        #pragma unroll
        for (int u = 0; u < 8; ++u) {
            estep(e,  xt[u], t + u);
            estep(el, xl[u], t + u - LAG);
            eo[u] = e;
            so[u] = make_float2(e.x - el.x, e.y - el.y);
        }

        size_t p = obase + (size_t)t * F_DIM;
        #pragma unroll
        for (int u = 0; u < 8; ++u)
            __stcs((float2*)(out + p + (size_t)u * F_DIM), eo[u]);
        #pragma unroll
        for (int u = 0; u < 8; ++u)
            __stcs((float2*)(out + NTOT + p + (size_t)u * F_DIM), so[u]);
        #pragma unroll
        for (int u = 0; u < 8; ++u) {
            float2 ab;
            ab.x = (so[u].x > 15.0f) ? 1.0f : 0.0f;
            ab.y = (so[u].y > 15.0f) ? 1.0f : 0.0f;
            __stcs((float2*)(out + 2 * NTOT + p + (size_t)u * F_DIM), ab);
        }
        #pragma unroll
        for (int u = 0; u < 8; ++u) {
            float2 bl;
            bl.x = (so[u].x < -15.0f) ? 1.0f : 0.0f;
            bl.y = (so[u].y < -15.0f) ? 1.0f : 0.0f;
            __stcs((float2*)(out + 3 * NTOT + p + (size_t)u * F_DIM), bl);
        }
        #pragma unroll
        for (int u = 0; u < 8; ++u) {
            float2 bt;
            bt.x = (so[u].x >= -15.0f && so[u].x <= 15.0f) ? 1.0f : 0.0f;
            bt.y = (so[u].y >= -15.0f && so[u].y <= 15.0f) ? 1.0f : 0.0f;
            __stcs((float2*)(out + 4 * NTOT + p + (size_t)u * F_DIM), bt);
        }
    }
}

extern "C" void kernel_launch(void* const* d_in, const int* in_sizes, int n_in,
                              void* d_out, int out_size) {
    const float* x = (const float*)d_in[0];
    float* out = (float*)d_out;
    int total = 32 * B_DIM * NC;        // 131072 threads
    ema_slope_filter_kernel<<<total / 128, 128>>>(x, out);
}